// round 7
// baseline (speedup 1.0000x reference)
#include <cuda_runtime.h>

#define NPTS 4096     // points per sample (nx*ny)
#define KN   30       // neighbors
#define HID  32       // MLP hidden width
#define TPB  256      // threads per block (one query per thread)

// Best-fit reference rounding chain (R2 form) :
//   pn = rn( rn(px*px) + rn(py*py) )       (no contraction)
//   t  = fma(qy,py, rn(qx*px))             (k-ascending fma chain, acc0 = 0)
//   d2 = rn( rn(qn - 2t) + pn )            (2t exact; left-to-right epilogue)
__device__ __forceinline__ float d2_ref(float qxx, float qyy, float qn,
                                        float px, float py, float pn) {
    float t = __fmaf_rn(qyy, py, __fmul_rn(qxx, px));
    return __fadd_rn(__fsub_rn(qn, __fmul_rn(2.0f, t)), pn);
}

// sp[i] = (px, py, px^2+py^2, label)
__global__ void __launch_bounds__(TPB) knn_itp_kernel(
    const float* __restrict__ u,
    const float* __restrict__ ix, const float* __restrict__ iy,
    const float* __restrict__ qx, const float* __restrict__ qy,
    const float* __restrict__ W1, const float* __restrict__ b1,
    const float* __restrict__ W2,
    float* __restrict__ out, int Q)
{
    extern __shared__ float4 sp[];                 // NPTS * 16 bytes = 64 KB
    __shared__ float sW1x[HID], sW1y[HID], sb1[HID], sW2[HID];

    const int s   = blockIdx.y;
    const int tid = threadIdx.x;

    // Stage candidate points + squared norms + labels into shared memory.
    for (int i = tid; i < NPTS; i += TPB) {
        float px = ix[s * NPTS + i];
        float py = iy[s * NPTS + i];
        float pn = __fadd_rn(__fmul_rn(px, px), __fmul_rn(py, py));
        sp[i] = make_float4(px, py, pn, u[s * NPTS + i]);
    }
    if (tid < HID) {
        sW1x[tid] = W1[tid];          // W1[0][i]
        sW1y[tid] = W1[HID + tid];    // W1[1][i]
        sb1[tid]  = b1[tid];
        sW2[tid]  = W2[tid];
    }
    __syncthreads();

    const int q = blockIdx.x * TPB + tid;
    const float qxx = __ldg(qx + s * Q + q);
    const float qyy = __ldg(qy + s * Q + q);
    const float qn  = __fadd_rn(__fmul_rn(qxx, qxx), __fmul_rn(qyy, qyy));

    // ---- exact top-30 smallest d2, lax.top_k tie semantics ----
    // Scan order means every id in the working set is < the incoming j, so:
    //  * strict (dd < mx): on an exact tie the incoming higher-index loses;
    //  * among tied maxima inside the set, evict the HIGHEST index.
    float d[KN];
    int   id[KN];
#pragma unroll
    for (int k = 0; k < KN; k++) {
        float4 p = sp[k];
        d[k]  = d2_ref(qxx, qyy, qn, p.x, p.y, p.z);
        id[k] = k;
    }
    float mx = d[0];
    int   ms = 0;
#pragma unroll
    for (int k = 1; k < KN; k++) {
        if (d[k] > mx || (d[k] == mx && id[k] > id[ms])) { mx = d[k]; ms = k; }
    }

    for (int j = KN; j < NPTS; j++) {
        float4 p = sp[j];
        float dd = d2_ref(qxx, qyy, qn, p.x, p.y, p.z);
        if (dd < mx) {
#pragma unroll
            for (int k = 0; k < KN; k++) if (k == ms) { d[k] = dd; id[k] = j; }
            mx = d[0]; ms = 0;
#pragma unroll
            for (int k = 1; k < KN; k++) {
                if (d[k] > mx || (d[k] == mx && id[k] > id[ms])) { mx = d[k]; ms = k; }
            }
        }
    }

    // ---- itp_model: logits = tanh(rel @ W1 + b1) @ W2 ; softmax over K ----
    float logit[KN];
    float lmax = -1e30f;
#pragma unroll
    for (int k = 0; k < KN; k++) {
        float4 p = sp[id[k]];
        float rx = p.x - qxx;
        float ry = p.y - qyy;
        float acc = 0.0f;
#pragma unroll
        for (int i = 0; i < HID; i++) {
            float h = tanhf(fmaf(rx, sW1x[i], fmaf(ry, sW1y[i], sb1[i])));
            acc = fmaf(h, sW2[i], acc);
        }
        logit[k] = acc;                 // b2 constant cancels in softmax
        lmax = fmaxf(lmax, acc);
    }
    float wsum = 0.0f, osum = 0.0f;
#pragma unroll
    for (int k = 0; k < KN; k++) {
        float w = expf(logit[k] - lmax);
        wsum += w;
        osum = fmaf(w, sp[id[k]].w, osum);
    }
    out[s * Q + q] = osum / wsum;
}

extern "C" void kernel_launch(void* const* d_in, const int* in_sizes, int n_in,
                              void* d_out, int out_size) {
    const float* u  = (const float*)d_in[0];
    const float* ix = (const float*)d_in[1];
    const float* iy = (const float*)d_in[2];
    const float* x  = (const float*)d_in[3];
    const float* y  = (const float*)d_in[4];
    const float* W1 = (const float*)d_in[5];
    const float* b1 = (const float*)d_in[6];
    const float* W2 = (const float*)d_in[7];
    // d_in[8] = b2 : constant shift, cancels in softmax
    float* out = (float*)d_out;

    const int nu = in_sizes[0] / NPTS;   // 4
    const int Q  = in_sizes[3] / nu;     // 16384

    cudaFuncSetAttribute(knn_itp_kernel,
                         cudaFuncAttributeMaxDynamicSharedMemorySize,
                         NPTS * (int)sizeof(float4));

    dim3 grid(Q / TPB, nu);
    knn_itp_kernel<<<grid, TPB, NPTS * sizeof(float4)>>>(
        u, ix, iy, x, y, W1, b1, W2, out, Q);
}

// round 8
// speedup vs baseline: 4.6325x; 4.6325x over previous
#include <cuda_runtime.h>

#define NPTS 4096     // points per sample (nx*ny)
#define KN   30       // neighbors
#define HID  32       // MLP hidden width
#define TPB  256      // threads per block
#define WARPS (TPB/32)
#define QPW  8        // queries per warp
#define FULL 0xffffffffu

#define POS_INF __int_as_float(0x7f800000)
#define NEG_INF __int_as_float(0xff800000)

// FROZEN reference rounding chain (validated bit-exact in R7):
//   pn = rn( rn(px*px) + rn(py*py) )
//   t  = fma(qy,py, rn(qx*px))
//   d2 = rn( rn(qn - 2t) + pn )
__device__ __forceinline__ float d2_ref(float qxx, float qyy, float qn,
                                        float px, float py, float pn) {
    float t = __fmaf_rn(qyy, py, __fmul_rn(qxx, px));
    return __fadd_rn(__fsub_rn(qn, __fmul_rn(2.0f, t)), pn);
}

// sp[i] = (px, py, px^2+py^2, label)
__global__ void __launch_bounds__(TPB) knn_itp_warp(
    const float* __restrict__ u,
    const float* __restrict__ ix, const float* __restrict__ iy,
    const float* __restrict__ qx, const float* __restrict__ qy,
    const float* __restrict__ W1, const float* __restrict__ b1,
    const float* __restrict__ W2,
    float* __restrict__ out, int Q)
{
    extern __shared__ float4 sp[];                 // 64 KB
    __shared__ float sW1x[HID], sW1y[HID], sb1[HID], sW2[HID];

    const int s    = blockIdx.y;
    const int tid  = threadIdx.x;
    const int lane = tid & 31;
    const int wid  = tid >> 5;

    for (int i = tid; i < NPTS; i += TPB) {
        float px = ix[s * NPTS + i];
        float py = iy[s * NPTS + i];
        float pn = __fadd_rn(__fmul_rn(px, px), __fmul_rn(py, py));
        sp[i] = make_float4(px, py, pn, u[s * NPTS + i]);
    }
    if (tid < HID) {
        sW1x[tid] = W1[tid];
        sW1y[tid] = W1[HID + tid];
        sb1[tid]  = b1[tid];
        sW2[tid]  = W2[tid];
    }
    __syncthreads();

    const int qbase = blockIdx.x * (WARPS * QPW) + wid * QPW;

    for (int qi = 0; qi < QPW; qi++) {
        const int q   = qbase + qi;
        const float qxx = qx[s * Q + q];          // broadcast load
        const float qyy = qy[s * Q + q];
        const float qn  = __fadd_rn(__fmul_rn(qxx, qxx), __fmul_rn(qyy, qyy));

        // Distributed top-30: lane k (<30) holds slot k, sorted DESCENDING by
        // lexicographic (d2, id). Lane 0 = current worst (eviction slot).
        // Lanes 30,31 hold -inf sentinels (never receive).
        float dv = (lane < KN) ? POS_INF : NEG_INF;
        int   iv = 0x7fffffff;

        for (int base = 0; base < NPTS; base += 32) {
            const int j = base + lane;
            float4 p = sp[j];
            float dd = d2_ref(qxx, qyy, qn, p.x, p.y, p.z);
            float d0 = __shfl_sync(FULL, dv, 0);
            // loose pre-filter (<=): superset of true accepts; exact lex recheck inside
            unsigned mask = __ballot_sync(FULL, dd <= d0);
            while (mask) {
                const int src = __ffs(mask) - 1; mask &= mask - 1;
                const float db = __shfl_sync(FULL, dd, src);
                const int   jb = base + src;
                d0 = __shfl_sync(FULL, dv, 0);
                const int i0 = __shfl_sync(FULL, iv, 0);
                if (db < d0 || (db == d0 && jb < i0)) {   // warp-uniform
                    const float dn = __shfl_down_sync(FULL, dv, 1);
                    const int   in_ = __shfl_down_sync(FULL, iv, 1);
                    if (lane < KN) {
                        // "greater" = evicted earlier: larger d2, or equal d2 & larger id
                        const bool next_gt = (dn > db) || (dn == db && in_ > jb);
                        const bool cur_gt  = (dv > db) || (dv == db && iv > jb);
                        const float dnew = next_gt ? dn  : (cur_gt ? db : dv);
                        const int   inew = next_gt ? in_ : (cur_gt ? jb : iv);
                        dv = dnew; iv = inew;
                    }
                }
            }
        }

        // ---- epilogue: lane k computes logit of neighbor k (bit-identical chain) ----
        float logit = NEG_INF;
        float lab   = 0.0f;
        if (lane < KN) {
            float4 p = sp[iv];
            lab = p.w;
            const float rx = p.x - qxx;
            const float ry = p.y - qyy;
            float acc = 0.0f;
#pragma unroll
            for (int i = 0; i < HID; i++) {
                float h = tanhf(fmaf(rx, sW1x[i], fmaf(ry, sW1y[i], sb1[i])));
                acc = fmaf(h, sW2[i], acc);
            }
            logit = acc;
        }
        float lmax = logit;
#pragma unroll
        for (int o = 16; o; o >>= 1) lmax = fmaxf(lmax, __shfl_xor_sync(FULL, lmax, o));
        const float w = (lane < KN) ? expf(logit - lmax) : 0.0f;
        float ws = w, os = w * lab;
#pragma unroll
        for (int o = 16; o; o >>= 1) {
            ws += __shfl_xor_sync(FULL, ws, o);
            os += __shfl_xor_sync(FULL, os, o);
        }
        if (lane == 0) out[s * Q + q] = os / ws;
    }
}

extern "C" void kernel_launch(void* const* d_in, const int* in_sizes, int n_in,
                              void* d_out, int out_size) {
    const float* u  = (const float*)d_in[0];
    const float* ix = (const float*)d_in[1];
    const float* iy = (const float*)d_in[2];
    const float* x  = (const float*)d_in[3];
    const float* y  = (const float*)d_in[4];
    const float* W1 = (const float*)d_in[5];
    const float* b1 = (const float*)d_in[6];
    const float* W2 = (const float*)d_in[7];
    // d_in[8] = b2 : constant shift, cancels in softmax
    float* out = (float*)d_out;

    const int nu = in_sizes[0] / NPTS;   // 4
    const int Q  = in_sizes[3] / nu;     // 16384

    cudaFuncSetAttribute(knn_itp_warp,
                         cudaFuncAttributeMaxDynamicSharedMemorySize,
                         NPTS * (int)sizeof(float4));

    dim3 grid(Q / (WARPS * QPW), nu);    // (256, 4)
    knn_itp_warp<<<grid, TPB, NPTS * sizeof(float4)>>>(
        u, ix, iy, x, y, W1, b1, W2, out, Q);
}

// round 9
// speedup vs baseline: 20.0176x; 4.3211x over previous
#include <cuda_runtime.h>
#include <math.h>

#define NPTS 4096
#define KN   30
#define HID  32
#define TPB  256
#define WARPS 8
#define QPW  8
#define GD   16              // grid cells per dim
#define NCELL (GD*GD)        // 256
#define CAP  128             // candidate buffer per query
#define FULL 0xffffffffu
#define MAXK 0xffffffffffffffffULL

// FROZEN reference rounding chain (validated bit-exact in R7/R8):
//   pn = rn( rn(px*px) + rn(py*py) )
//   t  = fma(qy,py, rn(qx*px))
//   d2 = rn( rn(qn - 2t) + pn )
__device__ __forceinline__ float d2_ref(float qxx, float qyy, float qn,
                                        float px, float py, float pn) {
    float t = __fmaf_rn(qyy, py, __fmul_rn(qxx, px));
    return __fadd_rn(__fsub_rn(qn, __fmul_rn(2.0f, t)), pn);
}

// order-preserving float->uint (handles tiny negatives from rounding)
__device__ __forceinline__ unsigned fkey(float f) {
    unsigned u = __float_as_uint(f);
    return u ^ (unsigned)(((int)u >> 31) | 0x80000000);
}

// cross-lane compare-exchange (element e = slot*32+lane, partner lane^j)
__device__ __forceinline__ void ceX(unsigned long long &v, int j, bool asc, int lane) {
    unsigned long long pv = __shfl_xor_sync(FULL, v, j);
    bool keepmin = (((lane & j) == 0) == asc);
    unsigned long long mn = v < pv ? v : pv;
    unsigned long long mx = v < pv ? pv : v;
    v = keepmin ? mn : mx;
}
// intra-lane compare-exchange between two slots
__device__ __forceinline__ void ceI(unsigned long long &a, unsigned long long &b, bool asc) {
    unsigned long long mn = a < b ? a : b;
    unsigned long long mx = a < b ? b : a;
    a = asc ? mn : mx;
    b = asc ? mx : mn;
}

// bitonic sort, 64 elements (2 slots/lane), e = slot*32 + lane, ascending
__device__ __forceinline__ void sort64(unsigned long long &v0, unsigned long long &v1, int lane) {
#pragma unroll
    for (int k = 2; k <= 16; k <<= 1) {
#pragma unroll
        for (int j = k >> 1; j > 0; j >>= 1) {
            bool asc = ((lane & k) == 0);
            ceX(v0, j, asc, lane); ceX(v1, j, asc, lane);
        }
    }
    // k=32: slot0 asc, slot1 desc
#pragma unroll
    for (int j = 16; j > 0; j >>= 1) { ceX(v0, j, true, lane); ceX(v1, j, false, lane); }
    // k=64: all asc
    ceI(v0, v1, true);
#pragma unroll
    for (int j = 16; j > 0; j >>= 1) { ceX(v0, j, true, lane); ceX(v1, j, true, lane); }
}

// bitonic sort, 128 elements (4 slots/lane), ascending
__device__ __forceinline__ void sort128(unsigned long long &v0, unsigned long long &v1,
                                        unsigned long long &v2, unsigned long long &v3, int lane) {
#pragma unroll
    for (int k = 2; k <= 16; k <<= 1) {
#pragma unroll
        for (int j = k >> 1; j > 0; j >>= 1) {
            bool asc = ((lane & k) == 0);
            ceX(v0, j, asc, lane); ceX(v1, j, asc, lane);
            ceX(v2, j, asc, lane); ceX(v3, j, asc, lane);
        }
    }
    // k=32: asc by slot T,F,T,F
#pragma unroll
    for (int j = 16; j > 0; j >>= 1) {
        ceX(v0, j, true, lane); ceX(v1, j, false, lane);
        ceX(v2, j, true, lane); ceX(v3, j, false, lane);
    }
    // k=64: slots {0,1} asc, {2,3} desc
    ceI(v0, v1, true); ceI(v2, v3, false);
#pragma unroll
    for (int j = 16; j > 0; j >>= 1) {
        ceX(v0, j, true, lane); ceX(v1, j, true, lane);
        ceX(v2, j, false, lane); ceX(v3, j, false, lane);
    }
    // k=128: all asc
    ceI(v0, v2, true); ceI(v1, v3, true);
    ceI(v0, v1, true); ceI(v2, v3, true);
#pragma unroll
    for (int j = 16; j > 0; j >>= 1) {
        ceX(v0, j, true, lane); ceX(v1, j, true, lane);
        ceX(v2, j, true, lane); ceX(v3, j, true, lane);
    }
}

// pb[i] = (px, py, original_index_bits, label), binned by 16x16 cell (row-major)
__global__ void __launch_bounds__(TPB) knn_grid(
    const float* __restrict__ u,
    const float* __restrict__ ix, const float* __restrict__ iy,
    const float* __restrict__ qx, const float* __restrict__ qy,
    const float* __restrict__ W1, const float* __restrict__ b1,
    const float* __restrict__ W2,
    float* __restrict__ out, int Q)
{
    extern __shared__ float4 pb[];                   // 64 KB binned points
    __shared__ int cellStart[NCELL + 1];
    __shared__ int cellCur[NCELL];
    __shared__ unsigned long long buf[WARPS][CAP];   // 8 KB
    __shared__ float sW1x[HID], sW1y[HID], sb1[HID], sW2[HID];

    const int s    = blockIdx.y;
    const int tid  = threadIdx.x;
    const int lane = tid & 31;
    const int w    = tid >> 5;

    // ---- bin points into 16x16 grid (counting sort) ----
    for (int c = tid; c < NCELL; c += TPB) cellCur[c] = 0;
    if (tid < HID) {
        sW1x[tid] = W1[tid];
        sW1y[tid] = W1[HID + tid];
        sb1[tid]  = b1[tid];
        sW2[tid]  = W2[tid];
    }
    __syncthreads();
    for (int i = tid; i < NPTS; i += TPB) {
        float px = ix[s * NPTS + i], py = iy[s * NPTS + i];
        int cx = min(GD - 1, (int)(px * GD));
        int cy = min(GD - 1, (int)(py * GD));
        atomicAdd(&cellCur[cy * GD + cx], 1);
    }
    __syncthreads();
    if (tid == 0) {
        int acc = 0;
        for (int c = 0; c < NCELL; c++) { cellStart[c] = acc; acc += cellCur[c]; }
        cellStart[NCELL] = acc;
    }
    __syncthreads();
    for (int c = tid; c < NCELL; c += TPB) cellCur[c] = cellStart[c];
    __syncthreads();
    for (int i = tid; i < NPTS; i += TPB) {
        float px = ix[s * NPTS + i], py = iy[s * NPTS + i];
        int cx = min(GD - 1, (int)(px * GD));
        int cy = min(GD - 1, (int)(py * GD));
        int pos = atomicAdd(&cellCur[cy * GD + cx], 1);
        pb[pos] = make_float4(px, py, __int_as_float(i), u[s * NPTS + i]);
    }
    __syncthreads();

    // ---- per-warp query loop ----
    const int qbase = blockIdx.x * (WARPS * QPW) + w * QPW;
    for (int qi = 0; qi < QPW; qi++) {
        const int q = qbase + qi;
        const float qxx = qx[s * Q + q];
        const float qyy = qy[s * Q + q];
        const float qn  = __fadd_rn(__fmul_rn(qxx, qxx), __fmul_rn(qyy, qyy));

        // threshold: radius with clipped-disk area covering ~64 expected points
        const float A = 64.0f / 4096.0f;
        float r = 0.0706f;
#pragma unroll
        for (int it = 0; it < 3; it++) {
            float ax = fminf(qxx, 1.0f - qxx) / r;
            float ay = fminf(qyy, 1.0f - qyy) / r;
            float fx = (ax >= 1.0f) ? 1.0f
                     : 1.0f - (acosf(ax) - ax * sqrtf(fmaxf(0.f, 1.f - ax * ax))) * 0.318309886f;
            float fy = (ay >= 1.0f) ? 1.0f
                     : 1.0f - (acosf(ay) - ay * sqrtf(fmaxf(0.f, 1.f - ay * ay))) * 0.318309886f;
            r = sqrtf(A / (3.14159265f * fx * fy));
        }
        float T = r * r;

        int cnt = 0;
        for (int attempt = 0; attempt < 16; attempt++) {
            cnt = 0;
            float rr = sqrtf(T) * 1.0002f;   // slack for d2-rounding vs true distance
            int cx0 = max(0,      (int)floorf((qxx - rr) * GD));
            int cx1 = min(GD - 1, (int)floorf((qxx + rr) * GD));
            int cy0 = max(0,      (int)floorf((qyy - rr) * GD));
            int cy1 = min(GD - 1, (int)floorf((qyy + rr) * GD));
            for (int cy = cy0; cy <= cy1; cy++) {
                const int b0 = cellStart[cy * GD + cx0];
                const int b1e = cellStart[cy * GD + cx1 + 1];
                for (int base = b0; base < b1e; base += 32) {
                    const int j = base + lane;
                    const bool act = (j < b1e);
                    float4 p = act ? pb[j] : make_float4(0.f, 0.f, 0.f, 0.f);
                    float pn = __fadd_rn(__fmul_rn(p.x, p.x), __fmul_rn(p.y, p.y));
                    float dd = d2_ref(qxx, qyy, qn, p.x, p.y, pn);
                    bool acc = act && (dd <= T);
                    unsigned m = __ballot_sync(FULL, acc);
                    if (acc) {
                        int off = cnt + __popc(m & ((1u << lane) - 1u));
                        if (off < CAP)
                            buf[w][off] = ((unsigned long long)fkey(dd) << 32)
                                        | (unsigned long long)__float_as_uint(p.z);
                    }
                    cnt += __popc(m);
                }
            }
            if (cnt >= KN && cnt <= CAP) break;
            T = (cnt > CAP) ? T * 0.6f : T * 2.0f;   // retry (rare by construction)
        }

        // ---- exact lex top-30 via bitonic sort of (d2,id) keys ----
        const int n = min(cnt, CAP);
        unsigned long long v0 = (lane      < n) ? buf[w][lane]      : MAXK;
        unsigned long long v1 = (32 + lane < n) ? buf[w][32 + lane] : MAXK;
        if (n <= 64) {
            sort64(v0, v1, lane);
        } else {
            unsigned long long v2 = (64 + lane < n) ? buf[w][64 + lane] : MAXK;
            unsigned long long v3 = (96 + lane < n) ? buf[w][96 + lane] : MAXK;
            sort128(v0, v1, v2, v3, lane);
        }
        // ranks 0..29 now live in slot0 of lanes 0..29

        // ---- epilogue (bit-identical chain to R7/R8) ----
        float logit = __int_as_float(0xff800000);
        float lab = 0.0f;
        if (lane < KN) {
            const int id = (int)(unsigned)(v0 & 0xffffffffULL);
            const float px = ix[s * NPTS + id];
            const float py = iy[s * NPTS + id];
            lab = u[s * NPTS + id];
            const float rx = px - qxx;
            const float ry = py - qyy;
            float acc = 0.0f;
#pragma unroll
            for (int i = 0; i < HID; i++) {
                float h = tanhf(fmaf(rx, sW1x[i], fmaf(ry, sW1y[i], sb1[i])));
                acc = fmaf(h, sW2[i], acc);
            }
            logit = acc;                 // b2 cancels in softmax
        }
        float lmax = logit;
#pragma unroll
        for (int o = 16; o; o >>= 1) lmax = fmaxf(lmax, __shfl_xor_sync(FULL, lmax, o));
        const float wgt = (lane < KN) ? expf(logit - lmax) : 0.0f;
        float ws = wgt, os = wgt * lab;
#pragma unroll
        for (int o = 16; o; o >>= 1) {
            ws += __shfl_xor_sync(FULL, ws, o);
            os += __shfl_xor_sync(FULL, os, o);
        }
        if (lane == 0) out[s * Q + q] = os / ws;
    }
}

extern "C" void kernel_launch(void* const* d_in, const int* in_sizes, int n_in,
                              void* d_out, int out_size) {
    const float* u  = (const float*)d_in[0];
    const float* ix = (const float*)d_in[1];
    const float* iy = (const float*)d_in[2];
    const float* x  = (const float*)d_in[3];
    const float* y  = (const float*)d_in[4];
    const float* W1 = (const float*)d_in[5];
    const float* b1 = (const float*)d_in[6];
    const float* W2 = (const float*)d_in[7];
    // d_in[8] = b2 : constant shift, cancels in softmax
    float* out = (float*)d_out;

    const int nu = in_sizes[0] / NPTS;   // 4
    const int Q  = in_sizes[3] / nu;     // 16384

    cudaFuncSetAttribute(knn_grid,
                         cudaFuncAttributeMaxDynamicSharedMemorySize,
                         NPTS * (int)sizeof(float4));

    dim3 grid(Q / (WARPS * QPW), nu);    // (256, 4)
    knn_grid<<<grid, TPB, NPTS * sizeof(float4)>>>(
        u, ix, iy, x, y, W1, b1, W2, out, Q);
}

// round 10
// speedup vs baseline: 39.4578x; 1.9712x over previous
#include <cuda_runtime.h>
#include <math.h>

#define NPTS 4096
#define KN   30
#define HID  32
#define GD   16
#define NCELL 256
#define CAP  64
#define TPB  512
#define WARPS 16
#define QPW  4
#define MAXNU 8
#define FULL 0xffffffffu
#define MAXK 0xffffffffffffffffULL
#define PI_F 3.14159265358979f

__device__ float4 g_pb[MAXNU][NPTS];
__device__ int    g_cs[MAXNU][NCELL + 1];

// FROZEN reference rounding chain (validated bit-exact R7-R9):
//   pn = rn( rn(px*px) + rn(py*py) )
//   t  = fma(qy,py, rn(qx*px))
//   d2 = rn( rn(qn - 2t) + pn )
__device__ __forceinline__ float d2_ref(float qxx, float qyy, float qn,
                                        float px, float py, float pn) {
    float t = __fmaf_rn(qyy, py, __fmul_rn(qxx, px));
    return __fadd_rn(__fsub_rn(qn, __fmul_rn(2.0f, t)), pn);
}

__device__ __forceinline__ unsigned fkey(float f) {
    unsigned u = __float_as_uint(f);
    return u ^ (unsigned)(((int)u >> 31) | 0x80000000);
}

__device__ __forceinline__ void ceX(unsigned long long &v, int j, bool asc, int lane) {
    unsigned long long pv = __shfl_xor_sync(FULL, v, j);
    bool keepmin = (((lane & j) == 0) == asc);
    unsigned long long mn = v < pv ? v : pv;
    unsigned long long mx = v < pv ? pv : v;
    v = keepmin ? mn : mx;
}

// ---- kernel 1: bin points into 16x16 grid, once per sample ----
__global__ void __launch_bounds__(256) bin_kernel(
    const float* __restrict__ u,
    const float* __restrict__ ix, const float* __restrict__ iy)
{
    __shared__ int cnts[NCELL];
    __shared__ int wsum[8];
    const int s = blockIdx.x, tid = threadIdx.x;
    const int lane = tid & 31, w = tid >> 5;

    cnts[tid] = 0;
    __syncthreads();
    for (int i = tid; i < NPTS; i += 256) {
        float px = ix[s * NPTS + i], py = iy[s * NPTS + i];
        int cx = min(GD - 1, (int)(px * GD));
        int cy = min(GD - 1, (int)(py * GD));
        atomicAdd(&cnts[cy * GD + cx], 1);
    }
    __syncthreads();
    // parallel exclusive prefix over 256 cells
    int v = cnts[tid];
    int inc = v;
#pragma unroll
    for (int o = 1; o < 32; o <<= 1) {
        int t = __shfl_up_sync(FULL, inc, o);
        if (lane >= o) inc += t;
    }
    if (lane == 31) wsum[w] = inc;
    __syncthreads();
    int base = 0;
    for (int k = 0; k < w; k++) base += wsum[k];
    int excl = base + inc - v;
    __syncthreads();
    cnts[tid] = excl;                 // reuse as scatter cursor
    g_cs[s][tid] = excl;
    if (tid == 255) g_cs[s][NCELL] = excl + v;
    __syncthreads();
    for (int i = tid; i < NPTS; i += 256) {
        float px = ix[s * NPTS + i], py = iy[s * NPTS + i];
        int cx = min(GD - 1, (int)(px * GD));
        int cy = min(GD - 1, (int)(py * GD));
        int pos = atomicAdd(&cnts[cy * GD + cx], 1);
        g_pb[s][pos] = make_float4(px, py, __int_as_float(i), u[s * NPTS + i]);
    }
}

// ---- kernel 2: per-warp query KNN + MLP-softmax blend ----
__global__ void __launch_bounds__(TPB, 3) knn_main(
    const float* __restrict__ qx, const float* __restrict__ qy,
    const float* __restrict__ W1, const float* __restrict__ b1,
    const float* __restrict__ W2,
    float* __restrict__ out, int Q)
{
    extern __shared__ float4 pb[];                   // 64 KB binned points
    __shared__ int cs[NCELL + 1];
    __shared__ unsigned long long buf[WARPS][CAP];   // 8 KB
    __shared__ float sW1x[HID], sW1y[HID], sb1[HID], sW2[HID];

    const int s    = blockIdx.y;
    const int tid  = threadIdx.x;
    const int lane = tid & 31;
    const int w    = tid >> 5;

    for (int i = tid; i < NPTS; i += TPB) pb[i] = g_pb[s][i];
    if (tid <= NCELL) cs[tid] = g_cs[s][tid];
    if (tid < HID) {
        sW1x[tid] = W1[tid];
        sW1y[tid] = W1[HID + tid];
        sb1[tid]  = b1[tid];
        sW2[tid]  = W2[tid];
    }
    __syncthreads();

    const int qbase = blockIdx.x * (WARPS * QPW) + w * QPW;
    for (int qi = 0; qi < QPW; qi++) {
        const int q = qbase + qi;
        const float qxx = qx[s * Q + q];
        const float qyy = qy[s * Q + q];
        const float qn  = __fadd_rn(__fmul_rn(qxx, qxx), __fmul_rn(qyy, qyy));

        // threshold radius: clipped-disk area targeting ~44 points
        const float A = 44.0f / 4096.0f;
        float r = 0.05851f;                          // sqrt(A/pi)
        const float mnx = fminf(qxx, 1.0f - qxx);
        const float mny = fminf(qyy, 1.0f - qyy);
        if (mnx < r || mny < r) {
#pragma unroll
            for (int it = 0; it < 2; it++) {
                float ax = fminf(mnx / r, 1.0f);
                float ay = fminf(mny / r, 1.0f);
                float fx = 1.0f - (acosf(ax) - ax * sqrtf(fmaxf(0.f, 1.f - ax * ax))) / PI_F;
                float fy = 1.0f - (acosf(ay) - ay * sqrtf(fmaxf(0.f, 1.f - ay * ay))) / PI_F;
                r = sqrtf(A / (PI_F * fx * fy));
            }
        }
        float T = r * r;

        int cnt = 0;
        for (int attempt = 0; attempt < 8; attempt++) {
            cnt = 0;
            const float rr = sqrtf(T) * 1.0002f;     // d2-rounding slack
            const int cx0 = max(0,      (int)floorf((qxx - rr) * GD));
            const int cx1 = min(GD - 1, (int)floorf((qxx + rr) * GD));
            const int cy0 = max(0,      (int)floorf((qyy - rr) * GD));
            const int cy1 = min(GD - 1, (int)floorf((qyy + rr) * GD));
            for (int cy = cy0; cy <= cy1; cy++) {
                const int b0  = cs[cy * GD + cx0];
                const int b1e = cs[cy * GD + cx1 + 1];
                for (int base = b0; base < b1e; base += 32) {
                    const int j = base + lane;
                    const bool act = (j < b1e);
                    float4 p = act ? pb[j] : make_float4(1e9f, 1e9f, 0.f, 0.f);
                    float pn = __fadd_rn(__fmul_rn(p.x, p.x), __fmul_rn(p.y, p.y));
                    float dd = d2_ref(qxx, qyy, qn, p.x, p.y, pn);
                    bool acc = act && (dd <= T);
                    unsigned m = __ballot_sync(FULL, acc);
                    if (acc) {
                        int off = cnt + __popc(m & ((1u << lane) - 1u));
                        if (off < CAP) {
                            unsigned id = (unsigned)__float_as_int(p.z);
                            buf[w][off] = ((unsigned long long)fkey(dd) << 24)
                                        | ((unsigned long long)id << 12)
                                        | (unsigned long long)j;
                        }
                    }
                    cnt += __popc(m);
                }
            }
            if (cnt >= KN && cnt <= CAP) break;
            T *= (cnt > CAP) ? (50.0f / (float)cnt)
                             : (45.0f / fmaxf((float)cnt, 8.0f));
        }

        // ---- exact smallest-32 selection (sorted) from <=64 keys ----
        const int n = min(cnt, CAP);
        unsigned long long v0 = (lane      < n) ? buf[w][lane]      : MAXK;
        unsigned long long v1 = (32 + lane < n) ? buf[w][32 + lane] : MAXK;
        // sort slot0 ascending, slot1 descending (shared sub-phases)
#pragma unroll
        for (int k = 2; k <= 16; k <<= 1) {
#pragma unroll
            for (int j = k >> 1; j > 0; j >>= 1) {
                bool asc = ((lane & k) == 0);
                ceX(v0, j, asc, lane);
                ceX(v1, j, asc, lane);
            }
        }
#pragma unroll
        for (int j = 16; j > 0; j >>= 1) { ceX(v0, j, true, lane); ceX(v1, j, false, lane); }
        // elementwise min -> bitonic sequence of the 32 smallest
        v0 = (v0 < v1) ? v0 : v1;
#pragma unroll
        for (int j = 16; j > 0; j >>= 1) ceX(v0, j, true, lane);
        // lanes 0..29 now hold exact lex top-30 (d2, id) ascending

        // ---- epilogue (bit-identical chain to R7-R9) ----
        float logit = __int_as_float(0xff800000);
        float lab = 0.0f;
        if (lane < KN) {
            const int pos = (int)(v0 & 0xFFFULL);
            const float4 p = pb[pos];
            lab = p.w;
            const float rx = p.x - qxx;
            const float ry = p.y - qyy;
            float acc = 0.0f;
#pragma unroll
            for (int i = 0; i < HID; i++) {
                float h = tanhf(fmaf(rx, sW1x[i], fmaf(ry, sW1y[i], sb1[i])));
                acc = fmaf(h, sW2[i], acc);
            }
            logit = acc;                 // b2 cancels in softmax
        }
        float lmax = logit;
#pragma unroll
        for (int o = 16; o; o >>= 1) lmax = fmaxf(lmax, __shfl_xor_sync(FULL, lmax, o));
        const float wgt = (lane < KN) ? expf(logit - lmax) : 0.0f;
        float ws = wgt, os = wgt * lab;
#pragma unroll
        for (int o = 16; o; o >>= 1) {
            ws += __shfl_xor_sync(FULL, ws, o);
            os += __shfl_xor_sync(FULL, os, o);
        }
        if (lane == 0) out[s * Q + q] = os / ws;
    }
}

extern "C" void kernel_launch(void* const* d_in, const int* in_sizes, int n_in,
                              void* d_out, int out_size) {
    const float* u  = (const float*)d_in[0];
    const float* ix = (const float*)d_in[1];
    const float* iy = (const float*)d_in[2];
    const float* x  = (const float*)d_in[3];
    const float* y  = (const float*)d_in[4];
    const float* W1 = (const float*)d_in[5];
    const float* b1 = (const float*)d_in[6];
    const float* W2 = (const float*)d_in[7];
    // d_in[8] = b2 : constant shift, cancels in softmax
    float* out = (float*)d_out;

    const int nu = in_sizes[0] / NPTS;   // 4
    const int Q  = in_sizes[3] / nu;     // 16384

    bin_kernel<<<nu, 256>>>(u, ix, iy);

    cudaFuncSetAttribute(knn_main,
                         cudaFuncAttributeMaxDynamicSharedMemorySize,
                         NPTS * (int)sizeof(float4));
    dim3 grid(Q / (WARPS * QPW), nu);    // (256, 4)
    knn_main<<<grid, TPB, NPTS * sizeof(float4)>>>(
        x, y, W1, b1, W2, out, Q);
}

// round 11
// speedup vs baseline: 43.7918x; 1.1098x over previous
#include <cuda_runtime.h>
#include <math.h>

#define NPTS 4096
#define KN   30
#define HID  32
#define GD   16
#define NCELL 256
#define CAP  64
#define TPB  512
#define WARPS 16
#define QPW  4
#define MAXNU 8
#define FULL 0xffffffffu
#define MAXK 0xffffffffffffffffULL
#define PI_F 3.14159265358979f

__device__ float4 g_pb[MAXNU][NPTS];
__device__ int    g_cs[MAXNU][NCELL + 1];

// FROZEN reference rounding chain (validated bit-exact R7-R10):
//   pn = rn( rn(px*px) + rn(py*py) )
//   t  = fma(qy,py, rn(qx*px))
//   d2 = rn( rn(qn - 2t) + pn )
__device__ __forceinline__ float d2_ref(float qxx, float qyy, float qn,
                                        float px, float py, float pn) {
    float t = __fmaf_rn(qyy, py, __fmul_rn(qxx, px));
    return __fadd_rn(__fsub_rn(qn, __fmul_rn(2.0f, t)), pn);
}

__device__ __forceinline__ unsigned fkey(float f) {
    unsigned u = __float_as_uint(f);
    return u ^ (unsigned)(((int)u >> 31) | 0x80000000);
}

// tanh via exact identity on MUFU (ex2 ~2ulp, rcp ~2ulp): abs err ~2e-7,
// smooth-only perturbation of logits (selection path unaffected)
__device__ __forceinline__ float fast_tanh(float x) {
    float t = __expf(2.0f * x);
    return __fdividef(t - 1.0f, t + 1.0f);
}

__device__ __forceinline__ void ceX(unsigned long long &v, int j, bool asc, int lane) {
    unsigned long long pv = __shfl_xor_sync(FULL, v, j);
    bool keepmin = (((lane & j) == 0) == asc);
    unsigned long long mn = v < pv ? v : pv;
    unsigned long long mx = v < pv ? pv : v;
    v = keepmin ? mn : mx;
}

// ---- kernel 1: bin points into 16x16 grid, once per sample ----
__global__ void __launch_bounds__(256) bin_kernel(
    const float* __restrict__ u,
    const float* __restrict__ ix, const float* __restrict__ iy)
{
    __shared__ int cnts[NCELL];
    __shared__ int wsum[8];
    const int s = blockIdx.x, tid = threadIdx.x;
    const int lane = tid & 31, w = tid >> 5;

    cnts[tid] = 0;
    __syncthreads();
    for (int i = tid; i < NPTS; i += 256) {
        float px = ix[s * NPTS + i], py = iy[s * NPTS + i];
        int cx = min(GD - 1, (int)(px * GD));
        int cy = min(GD - 1, (int)(py * GD));
        atomicAdd(&cnts[cy * GD + cx], 1);
    }
    __syncthreads();
    int v = cnts[tid];
    int inc = v;
#pragma unroll
    for (int o = 1; o < 32; o <<= 1) {
        int t = __shfl_up_sync(FULL, inc, o);
        if (lane >= o) inc += t;
    }
    if (lane == 31) wsum[w] = inc;
    __syncthreads();
    int base = 0;
    for (int k = 0; k < w; k++) base += wsum[k];
    int excl = base + inc - v;
    __syncthreads();
    cnts[tid] = excl;
    g_cs[s][tid] = excl;
    if (tid == 255) g_cs[s][NCELL] = excl + v;
    __syncthreads();
    for (int i = tid; i < NPTS; i += 256) {
        float px = ix[s * NPTS + i], py = iy[s * NPTS + i];
        int cx = min(GD - 1, (int)(px * GD));
        int cy = min(GD - 1, (int)(py * GD));
        int pos = atomicAdd(&cnts[cy * GD + cx], 1);
        g_pb[s][pos] = make_float4(px, py, __int_as_float(i), u[s * NPTS + i]);
    }
}

// ---- kernel 2: per-warp query KNN + MLP-softmax blend ----
__global__ void __launch_bounds__(TPB, 3) knn_main(
    const float* __restrict__ qx, const float* __restrict__ qy,
    const float* __restrict__ W1, const float* __restrict__ b1,
    const float* __restrict__ W2,
    float* __restrict__ out, int Q)
{
    extern __shared__ float4 pb[];                   // 64 KB binned points
    __shared__ int cs[NCELL + 1];
    __shared__ unsigned long long buf[WARPS][CAP];   // 8 KB
    __shared__ float sW1x[HID], sW1y[HID], sb1[HID], sW2[HID];

    const int s    = blockIdx.y;
    const int tid  = threadIdx.x;
    const int lane = tid & 31;
    const int w    = tid >> 5;

    for (int i = tid; i < NPTS; i += TPB) pb[i] = g_pb[s][i];
    if (tid <= NCELL) cs[tid] = g_cs[s][tid];
    if (tid < HID) {
        sW1x[tid] = W1[tid];
        sW1y[tid] = W1[HID + tid];
        sb1[tid]  = b1[tid];
        sW2[tid]  = W2[tid];
    }
    __syncthreads();

    const int qbase = blockIdx.x * (WARPS * QPW) + w * QPW;
    for (int qi = 0; qi < QPW; qi++) {
        const int q = qbase + qi;
        const float qxx = qx[s * Q + q];
        const float qyy = qy[s * Q + q];
        const float qn  = __fadd_rn(__fmul_rn(qxx, qxx), __fmul_rn(qyy, qyy));

        // threshold radius: clipped-disk area targeting ~44 points
        const float A = 44.0f / 4096.0f;
        float r = 0.05851f;                          // sqrt(A/pi)
        const float mnx = fminf(qxx, 1.0f - qxx);
        const float mny = fminf(qyy, 1.0f - qyy);
        if (mnx < r || mny < r) {
#pragma unroll
            for (int it = 0; it < 2; it++) {
                float ax = fminf(mnx / r, 1.0f);
                float ay = fminf(mny / r, 1.0f);
                float fx = 1.0f - (acosf(ax) - ax * sqrtf(fmaxf(0.f, 1.f - ax * ax))) / PI_F;
                float fy = 1.0f - (acosf(ay) - ay * sqrtf(fmaxf(0.f, 1.f - ay * ay))) / PI_F;
                r = sqrtf(A / (PI_F * fx * fy));
            }
        }
        float T = r * r;

        int cnt = 0;
        for (int attempt = 0; attempt < 8; attempt++) {
            cnt = 0;
            const float rr = sqrtf(T) * 1.0002f;     // d2-rounding slack
            const int cx0 = max(0,      (int)floorf((qxx - rr) * GD));
            const int cx1 = min(GD - 1, (int)floorf((qxx + rr) * GD));
            const int cy0 = max(0,      (int)floorf((qyy - rr) * GD));
            const int cy1 = min(GD - 1, (int)floorf((qyy + rr) * GD));
            for (int cy = cy0; cy <= cy1; cy++) {
                const int b0  = cs[cy * GD + cx0];
                const int b1e = cs[cy * GD + cx1 + 1];
                for (int base = b0; base < b1e; base += 32) {
                    const int j = base + lane;
                    const bool act = (j < b1e);
                    float4 p = act ? pb[j] : make_float4(1e9f, 1e9f, 0.f, 0.f);
                    float pn = __fadd_rn(__fmul_rn(p.x, p.x), __fmul_rn(p.y, p.y));
                    float dd = d2_ref(qxx, qyy, qn, p.x, p.y, pn);
                    bool acc = act && (dd <= T);
                    unsigned m = __ballot_sync(FULL, acc);
                    if (acc) {
                        int off = cnt + __popc(m & ((1u << lane) - 1u));
                        if (off < CAP) {
                            unsigned id = (unsigned)__float_as_int(p.z);
                            buf[w][off] = ((unsigned long long)fkey(dd) << 24)
                                        | ((unsigned long long)id << 12)
                                        | (unsigned long long)j;
                        }
                    }
                    cnt += __popc(m);
                }
            }
            if (cnt >= KN && cnt <= CAP) break;
            T *= (cnt > CAP) ? (50.0f / (float)cnt)
                             : (45.0f / fmaxf((float)cnt, 8.0f));
        }

        // ---- exact smallest-32 selection (sorted) from <=64 keys ----
        const int n = min(cnt, CAP);
        unsigned long long v0 = (lane      < n) ? buf[w][lane]      : MAXK;
        unsigned long long v1 = (32 + lane < n) ? buf[w][32 + lane] : MAXK;
#pragma unroll
        for (int k = 2; k <= 16; k <<= 1) {
#pragma unroll
            for (int j = k >> 1; j > 0; j >>= 1) {
                bool asc = ((lane & k) == 0);
                ceX(v0, j, asc, lane);
                ceX(v1, j, asc, lane);
            }
        }
#pragma unroll
        for (int j = 16; j > 0; j >>= 1) { ceX(v0, j, true, lane); ceX(v1, j, false, lane); }
        v0 = (v0 < v1) ? v0 : v1;
#pragma unroll
        for (int j = 16; j > 0; j >>= 1) ceX(v0, j, true, lane);
        // lanes 0..29 hold exact lex top-30 (d2, id) ascending

        // ---- epilogue: MUFU-based tanh/exp (smooth ~2ulp noise only) ----
        float logit = __int_as_float(0xff800000);
        float lab = 0.0f;
        if (lane < KN) {
            const int pos = (int)(v0 & 0xFFFULL);
            const float4 p = pb[pos];
            lab = p.w;
            const float rx = p.x - qxx;
            const float ry = p.y - qyy;
            float acc = 0.0f;
#pragma unroll
            for (int i = 0; i < HID; i++) {
                float h = fast_tanh(fmaf(rx, sW1x[i], fmaf(ry, sW1y[i], sb1[i])));
                acc = fmaf(h, sW2[i], acc);
            }
            logit = acc;                 // b2 cancels in softmax
        }
        float lmax = logit;
#pragma unroll
        for (int o = 16; o; o >>= 1) lmax = fmaxf(lmax, __shfl_xor_sync(FULL, lmax, o));
        const float wgt = (lane < KN) ? __expf(logit - lmax) : 0.0f;
        float ws = wgt, os = wgt * lab;
#pragma unroll
        for (int o = 16; o; o >>= 1) {
            ws += __shfl_xor_sync(FULL, ws, o);
            os += __shfl_xor_sync(FULL, os, o);
        }
        if (lane == 0) out[s * Q + q] = __fdividef(os, ws);
    }
}

extern "C" void kernel_launch(void* const* d_in, const int* in_sizes, int n_in,
                              void* d_out, int out_size) {
    const float* u  = (const float*)d_in[0];
    const float* ix = (const float*)d_in[1];
    const float* iy = (const float*)d_in[2];
    const float* x  = (const float*)d_in[3];
    const float* y  = (const float*)d_in[4];
    const float* W1 = (const float*)d_in[5];
    const float* b1 = (const float*)d_in[6];
    const float* W2 = (const float*)d_in[7];
    // d_in[8] = b2 : constant shift, cancels in softmax
    float* out = (float*)d_out;

    const int nu = in_sizes[0] / NPTS;   // 4
    const int Q  = in_sizes[3] / nu;     // 16384

    bin_kernel<<<nu, 256>>>(u, ix, iy);

    cudaFuncSetAttribute(knn_main,
                         cudaFuncAttributeMaxDynamicSharedMemorySize,
                         NPTS * (int)sizeof(float4));
    dim3 grid(Q / (WARPS * QPW), nu);    // (256, 4)
    knn_main<<<grid, TPB, NPTS * sizeof(float4)>>>(
        x, y, W1, b1, W2, out, Q);
}